// round 10
// baseline (speedup 1.0000x reference)
#include <cuda_runtime.h>
#include <math.h>

#define FULL 0xFFFFFFFFu
#define T_LEN 2048
#define CHUNKS 16          // 16 chunks x 128 elems = 2048
#define ROWS_PER_BLOCK 4   // 8 warps: 2 warps per row (half 0 / half 1)

// streaming sums for one chunk (e,m known, global chunk index i)
#define SUMS(e, m, i)                                                     \
    do {                                                                  \
        sumt = fmaf((m).x, (e).x, sumt); sumt = fmaf((m).y, (e).y, sumt); \
        sumt = fmaf((m).z, (e).z, sumt); sumt = fmaf((m).w, (e).w, sumt); \
        const float cnt_ = ((m).x + (m).y) + ((m).z + (m).w);             \
        csum += cnt_;                                                     \
        const float base_ = (float)(128 * (i) + 4 * lane);                \
        sumidx = fmaf(cnt_, base_, sumidx);                               \
        sumidx += fmaf(3.f, (m).w, fmaf(2.f, (m).z, (m).y));              \
    } while (0)

__global__ __launch_bounds__(256, 4)
void scpp_kernel(const float* __restrict__ event_times,
                 const float* __restrict__ input_mask,
                 const float* __restrict__ t0p,
                 const float* __restrict__ t1p,
                 const float* __restrict__ mup,
                 const float* __restrict__ betap,
                 float* __restrict__ out)
{
    const int lane = threadIdx.x & 31;
    const int w    = threadIdx.x >> 5;
    const int r    = w >> 1;          // row slot within block (0..3)
    const int half = w & 1;           // 0: chunks 0-7, 1: chunks 8-15
    const int row  = blockIdx.x * ROWS_PER_BLOCK + r;

    const float mu   = log1pf(expf(__ldg(mup)));
    const float beta = log1pf(expf(__ldg(betap)));
    const float t0   = __ldg(t0p);
    const float t1   = __ldg(t1p);

    const size_t rbase = (size_t)row * T_LEN;
    const float4* ev = reinterpret_cast<const float4*>(event_times + rbase);
    const float4* mk = reinterpret_cast<const float4*>(input_mask  + rbase);

    float sumt = 0.f;     // sum mask * t              (own half)
    float sumidx = 0.f;   // sum mask * index          (own half, exact)
    float csum = 0.f;     // sum mask                  (own half)
    float S = 0.f;        // sum masked exp(mu*t - beta*k)  (warp A only)

    __shared__ float sm[ROWS_PER_BLOCK][2][4];   // sumt, sumidx, S, count

    if (half == 0) {
        // ===== warp A: chunks 0..7, owns all exp/scan work =====
        // front-batch: chunks 0,1 + prefetch 2..5
        const float4 a0e = ev[lane +  0], a1e = ev[lane + 32];
        const float4 a0m = mk[lane +  0], a1m = mk[lane + 32];
        const float4 p0e = ev[lane + 32*2], p1e = ev[lane + 32*3];
        const float4 p2e = ev[lane + 32*4], p3e = ev[lane + 32*5];
        const float4 p0m = mk[lane + 32*2], p1m = mk[lane + 32*3];
        const float4 p2m = mk[lane + 32*4], p3m = mk[lane + 32*5];

        float T = 0.f;    // running masked count for exp gating (warp-uniform)

        #pragma unroll
        for (int i = 0; i < 2; i++) {
            const float4 e = (i == 0) ? a0e : a1e;
            const float4 m = (i == 0) ? a0m : a1m;

            SUMS(e, m, i);
            const float cnt = (m.x + m.y) + (m.z + m.w);

            float s = cnt;
            #pragma unroll
            for (int off = 1; off < 32; off <<= 1) {
                const float u = __shfl_up_sync(FULL, s, off);
                if (lane >= off) s += u;
            }

            if (beta * T < 104.f) {    // expf underflow bound
                float k = T + (s - cnt);
                if (m.x > 0.5f) { S += expf(fmaf(mu, e.x, -beta * k)); k += 1.f; }
                if (m.y > 0.5f) { S += expf(fmaf(mu, e.y, -beta * k)); k += 1.f; }
                if (m.z > 0.5f) { S += expf(fmaf(mu, e.z, -beta * k)); k += 1.f; }
                if (m.w > 0.5f) { S += expf(fmaf(mu, e.w, -beta * k)); }
            }
            T += __shfl_sync(FULL, s, 31);
        }

        // rare fallback (arbitrary masks): continue scan+exp over chunks 2..15,
        // reloading; computes ONLY S (gating via T), never touches sumt/sumidx/csum.
        if (beta * T < 106.f) {
            for (int i = 2; i < CHUNKS; i++) {
                const float4 e = ev[lane + 32 * i];
                const float4 m = mk[lane + 32 * i];
                const float cnt = (m.x + m.y) + (m.z + m.w);
                float s = cnt;
                #pragma unroll
                for (int off = 1; off < 32; off <<= 1) {
                    const float u = __shfl_up_sync(FULL, s, off);
                    if (lane >= off) s += u;
                }
                if (beta * T < 104.f) {
                    float k = T + (s - cnt);
                    if (m.x > 0.5f) { S += expf(fmaf(mu, e.x, -beta * k)); k += 1.f; }
                    if (m.y > 0.5f) { S += expf(fmaf(mu, e.y, -beta * k)); k += 1.f; }
                    if (m.z > 0.5f) { S += expf(fmaf(mu, e.z, -beta * k)); k += 1.f; }
                    if (m.w > 0.5f) { S += expf(fmaf(mu, e.w, -beta * k)); }
                }
                T += __shfl_sync(FULL, s, 31);
                if (beta * T >= 106.f) break;
            }
        }

        // streaming 2..7: consume prefetched 2..5 while 6,7 load
        const float4 q0e = ev[lane + 32*6], q1e = ev[lane + 32*7];
        const float4 q0m = mk[lane + 32*6], q1m = mk[lane + 32*7];
        SUMS(p0e, p0m, 2); SUMS(p1e, p1m, 3); SUMS(p2e, p2m, 4); SUMS(p3e, p3m, 5);
        SUMS(q0e, q0m, 6); SUMS(q1e, q1m, 7);
    } else {
        // ===== warp B: chunks 8..15, pure streaming (exp terms are exact 0) =====
        float4 p0e = ev[lane + 32*8],  p1e = ev[lane + 32*9];
        float4 p2e = ev[lane + 32*10], p3e = ev[lane + 32*11];
        float4 p0m = mk[lane + 32*8],  p1m = mk[lane + 32*9];
        float4 p2m = mk[lane + 32*10], p3m = mk[lane + 32*11];

        const float4 q0e = ev[lane + 32*12], q1e = ev[lane + 32*13];
        const float4 q2e = ev[lane + 32*14], q3e = ev[lane + 32*15];
        const float4 q0m = mk[lane + 32*12], q1m = mk[lane + 32*13];
        const float4 q2m = mk[lane + 32*14], q3m = mk[lane + 32*15];
        SUMS(p0e, p0m, 8);  SUMS(p1e, p1m, 9);
        SUMS(p2e, p2m, 10); SUMS(p3e, p3m, 11);
        SUMS(q0e, q0m, 12); SUMS(q1e, q1m, 13);
        SUMS(q2e, q2m, 14); SUMS(q3e, q3m, 15);
    }

    // ===== warp reductions (4 values) =====
    #pragma unroll
    for (int off = 16; off; off >>= 1) {
        sumt   += __shfl_down_sync(FULL, sumt,   off);
        sumidx += __shfl_down_sync(FULL, sumidx, off);
        csum   += __shfl_down_sync(FULL, csum,   off);
        S      += __shfl_down_sync(FULL, S,      off);
    }

    if (lane == 0) {
        sm[r][half][0] = sumt;
        sm[r][half][1] = sumidx;
        sm[r][half][2] = S;
        sm[r][half][3] = csum;
    }
    __syncthreads();

    if (half == 0 && lane == 0) {
        const float st = sm[r][0][0] + sm[r][1][0];
        const float si = sm[r][0][1] + sm[r][1][1];
        const float Ss = sm[r][0][2] + sm[r][1][2];
        const float Mt = sm[r][0][3] + sm[r][1][3];   // total masked count

        const float ll  = fmaf(mu, st, -beta * si);
        const float emb = expf(-beta);
        // telescoped compensator: (1-e^{-b})*S - e^{mu*t0} + e^{mu*t1 - b*M}
        float comp = fmaf(1.f - emb, Ss, -expf(mu * t0));
        comp += expf(fmaf(mu, t1, -beta * Mt));       // exact 0 after underflow
        out[row] = ll - comp / mu;
    }
}

extern "C" void kernel_launch(void* const* d_in, const int* in_sizes, int n_in,
                              void* d_out, int out_size)
{
    const float* event_times = (const float*)d_in[0];
    // d_in[1] = spatial_locations : unused by the op
    const float* input_mask  = (const float*)d_in[2];
    const float* t0          = (const float*)d_in[3];
    const float* t1          = (const float*)d_in[4];
    const float* mu_param    = (const float*)d_in[5];
    const float* beta_param  = (const float*)d_in[6];
    float* out = (float*)d_out;

    const int n_rows = out_size;  // 8192
    scpp_kernel<<<n_rows / ROWS_PER_BLOCK, 256>>>(event_times, input_mask,
                                                  t0, t1, mu_param, beta_param, out);
}